// round 1
// baseline (speedup 1.0000x reference)
#include <cuda_runtime.h>
#include <cstdint>

#define BB 16
#define SS 2048
#define DD 512

// ---------------- device scratch (allocation-free rule: __device__ globals) ---
__device__ float g_a[BB * SS];                    // dot(frame[t], w1)
__device__ float g_c[BB * SS];                    // dot(frame[t], w2)
__device__ int   g_segstart[BB * (SS + 1)];       // per batch: start frame of each segment; [nw] = SS
__device__ int   g_nwords[BB];
__device__ float g_mean[(size_t)BB * SS * DD];    // 64 MB segment means (only first nw rows/batch valid)

// ---------------- K1: per-frame score dots --------------------------------
// one warp per frame row (512 floats), two dot products, warp reduce.
__global__ void k_scores(const float* __restrict__ frame, const float* __restrict__ wscore) {
    int warp = (blockIdx.x * blockDim.x + threadIdx.x) >> 5;
    int lane = threadIdx.x & 31;
    if (warp >= BB * SS) return;
    const float4* row = (const float4*)(frame + (size_t)warp * DD);
    const float4* w1  = (const float4*)wscore;
    const float4* w2  = (const float4*)(wscore + DD);
    float d1 = 0.f, d2 = 0.f;
#pragma unroll
    for (int k = 0; k < 4; k++) {
        int i = lane + k * 32;                    // 128 float4 per row
        float4 f = row[i];
        float4 a = w1[i];
        float4 b = w2[i];
        d1 += f.x * a.x + f.y * a.y + f.z * a.z + f.w * a.w;
        d2 += f.x * b.x + f.y * b.y + f.z * b.z + f.w * b.w;
    }
#pragma unroll
    for (int off = 16; off; off >>= 1) {
        d1 += __shfl_down_sync(0xFFFFFFFFu, d1, off);
        d2 += __shfl_down_sync(0xFFFFFFFFu, d2, off);
    }
    if (lane == 0) { g_a[warp] = d1; g_c[warp] = d2; }
}

// ---------------- K2: per-batch segment scan --------------------------------
// 1 block per batch row, 1024 threads, 2 time steps per thread.
// starts[t] = (t==0) ? 0 : !(score[t-1] > 0.5);  seg = inclusive cumsum(starts)
__global__ void k_scan(const float* __restrict__ bscore_p, float* __restrict__ out_tail) {
    int b   = blockIdx.x;
    int tid = threadIdx.x;                        // 0..1023
    float bs = *bscore_p;
    int t0 = tid * 2, t1 = t0 + 1;
    // fuse[p] = (g_a[p] + g_c[p+1] + bs) > 0.5 ; starts[t] = 1 - fuse[t-1]
    int s0 = (t0 == 0) ? 0
             : (((g_a[b * SS + t0 - 1] + g_c[b * SS + t0] + bs) > 0.5f) ? 0 : 1);
    int s1 = (((g_a[b * SS + t1 - 1] + g_c[b * SS + t1] + bs) > 0.5f) ? 0 : 1);

    __shared__ int sc[1024];
    sc[tid] = s0 + s1;
    __syncthreads();
    for (int off = 1; off < 1024; off <<= 1) {
        int v   = sc[tid];
        int add = (tid >= off) ? sc[tid - off] : 0;
        __syncthreads();
        sc[tid] = v + add;
        __syncthreads();
    }
    int excl = (tid == 0) ? 0 : sc[tid - 1];      // pairs before this thread
    int seg0 = excl + s0;
    int seg1 = excl + s0 + s1;

    int base = b * (SS + 1);
    if (t0 == 0 || s0 == 1) g_segstart[base + seg0] = t0;
    if (s1 == 1)            g_segstart[base + seg1] = t1;
    if (t1 == SS - 1) {
        int nw = seg1 + 1;
        g_nwords[b] = nw;
        g_segstart[base + nw] = SS;               // sentinel end
        if (out_tail) out_tail[b] = (float)nw;    // n_words output (as float)
    }
}

// ---------------- K3: segment means --------------------------------
// one block (128 threads) per candidate word; each thread owns one float4 column group.
__global__ void k_mean(const float* __restrict__ frame) {
    int j = blockIdx.x;                           // 0 .. B*S-1
    int b = j / SS, w = j % SS;
    if (w >= g_nwords[b]) return;
    int base = b * (SS + 1);
    int st = g_segstart[base + w];
    int en = g_segstart[base + w + 1];
    float inv = 1.0f / (float)(en - st);
    int tid = threadIdx.x;                        // 0..127
    float4 acc = make_float4(0.f, 0.f, 0.f, 0.f);
    for (int t = st; t < en; t++) {
        float4 f = ((const float4*)(frame + ((size_t)(b * SS + t)) * DD))[tid];
        acc.x += f.x; acc.y += f.y; acc.z += f.z; acc.w += f.w;
    }
    acc.x *= inv; acc.y *= inv; acc.z *= inv; acc.w *= inv;
    ((float4*)(g_mean + (size_t)j * DD))[tid] = acc;
}

// ---------------- K4: words = mean @ w_comb + b_comb (valid rows), zeros otherwise
// classic fp32 tiled GEMM: 64x64 tile per 256-thread block, BK=16, 4x4 per thread.
__global__ void k_gemm(const float* __restrict__ wc, const float* __restrict__ bc,
                       float* __restrict__ out) {
    int b    = blockIdx.z;
    int row0 = blockIdx.y * 64;
    int col0 = blockIdx.x * 64;
    int nw   = g_nwords[b];
    int tid  = threadIdx.x;
    float* outbase = out + (size_t)b * SS * DD;

    if (row0 >= nw) {
        // fully padded tile: just write zeros (d_out is poisoned).
        float4 z = make_float4(0.f, 0.f, 0.f, 0.f);
        for (int i = tid; i < 64 * 16; i += 256) {
            int r = i >> 4, cq = i & 15;
            ((float4*)(outbase + (size_t)(row0 + r) * DD + col0))[cq] = z;
        }
        return;
    }

    __shared__ float As[16][64];
    __shared__ float Bs[16][64];
    const float* A = g_mean + (size_t)b * SS * DD;

    float acc[4][4];
#pragma unroll
    for (int i = 0; i < 4; i++)
#pragma unroll
        for (int j = 0; j < 4; j++) acc[i][j] = 0.f;

    int tx = tid & 15, ty = tid >> 4;

    for (int k0 = 0; k0 < DD; k0 += 16) {
        {   // A tile: 64 rows x 16 k, transposed into As[k][row]
            int r = tid >> 2, kq = tid & 3;
            float4 v = *(const float4*)(A + (size_t)(row0 + r) * DD + k0 + kq * 4);
            As[kq * 4 + 0][r] = v.x;
            As[kq * 4 + 1][r] = v.y;
            As[kq * 4 + 2][r] = v.z;
            As[kq * 4 + 3][r] = v.w;
        }
        {   // B tile: 16 k x 64 cols
            int k = tid >> 4, cq = tid & 15;
            float4 v = *(const float4*)(wc + (size_t)(k0 + k) * DD + col0 + cq * 4);
            *(float4*)&Bs[k][cq * 4] = v;
        }
        __syncthreads();
#pragma unroll
        for (int k = 0; k < 16; k++) {
            float4 a = *(float4*)&As[k][ty * 4];
            float4 bv = *(float4*)&Bs[k][tx * 4];
            acc[0][0] += a.x * bv.x; acc[0][1] += a.x * bv.y; acc[0][2] += a.x * bv.z; acc[0][3] += a.x * bv.w;
            acc[1][0] += a.y * bv.x; acc[1][1] += a.y * bv.y; acc[1][2] += a.y * bv.z; acc[1][3] += a.y * bv.w;
            acc[2][0] += a.z * bv.x; acc[2][1] += a.z * bv.y; acc[2][2] += a.z * bv.z; acc[2][3] += a.z * bv.w;
            acc[3][0] += a.w * bv.x; acc[3][1] += a.w * bv.y; acc[3][2] += a.w * bv.z; acc[3][3] += a.w * bv.w;
        }
        __syncthreads();
    }

    float4 bias = *(const float4*)(bc + col0 + tx * 4);
#pragma unroll
    for (int i = 0; i < 4; i++) {
        int r = row0 + ty * 4 + i;
        float4 v;
        if (r < nw) {
            v.x = acc[i][0] + bias.x;
            v.y = acc[i][1] + bias.y;
            v.z = acc[i][2] + bias.z;
            v.w = acc[i][3] + bias.w;
        } else {
            v = make_float4(0.f, 0.f, 0.f, 0.f);
        }
        *(float4*)(outbase + (size_t)r * DD + col0 + tx * 4) = v;
    }
}

// ---------------- launcher ----------------
extern "C" void kernel_launch(void* const* d_in, const int* in_sizes, int n_in,
                              void* d_out, int out_size) {
    const float* frame  = (const float*)d_in[0];   // [B,S,D]
    const float* wscore = (const float*)d_in[1];   // [2D,1]
    const float* bscore = (const float*)d_in[2];   // [1]
    const float* wcomb  = (const float*)d_in[3];   // [D,D]
    const float* bcomb  = (const float*)d_in[4];   // [D]
    float* out = (float*)d_out;

    float* tail = (out_size >= BB * SS * DD + BB) ? out + (size_t)BB * SS * DD : nullptr;

    k_scores<<<(BB * SS) / 8, 256>>>(frame, wscore);
    k_scan<<<BB, 1024>>>(bscore, tail);
    k_mean<<<BB * SS, 128>>>(frame);
    dim3 grid(DD / 64, SS / 64, BB);
    k_gemm<<<grid, 256>>>(wcomb, bcomb, out);
}

// round 3
// speedup vs baseline: 2.5334x; 2.5334x over previous
#include <cuda_runtime.h>
#include <cstdint>

#define BB 16
#define SS 2048
#define DD 512

// ---------------- device scratch (allocation-free rule: __device__ globals) ---
__device__ float g_a[BB * SS];                    // dot(frame[t], w1)
__device__ float g_c[BB * SS];                    // dot(frame[t], w2)
__device__ int   g_segstart[BB * (SS + 1)];       // per batch: start frame of each segment; [nw] = SS
__device__ int   g_nwords[BB];
__device__ float g_mean[(size_t)BB * SS * DD];    // 64 MB segment means (only first nw rows/batch valid)

// ---------------- K1: per-frame score dots --------------------------------
__global__ void k_scores(const float* __restrict__ frame, const float* __restrict__ wscore) {
    int warp = (blockIdx.x * blockDim.x + threadIdx.x) >> 5;
    int lane = threadIdx.x & 31;
    if (warp >= BB * SS) return;
    const float4* row = (const float4*)(frame + (size_t)warp * DD);
    const float4* w1  = (const float4*)wscore;
    const float4* w2  = (const float4*)(wscore + DD);
    float d1 = 0.f, d2 = 0.f;
#pragma unroll
    for (int k = 0; k < 4; k++) {
        int i = lane + k * 32;
        float4 f = row[i];
        float4 a = w1[i];
        float4 b = w2[i];
        d1 += f.x * a.x + f.y * a.y + f.z * a.z + f.w * a.w;
        d2 += f.x * b.x + f.y * b.y + f.z * b.z + f.w * b.w;
    }
#pragma unroll
    for (int off = 16; off; off >>= 1) {
        d1 += __shfl_down_sync(0xFFFFFFFFu, d1, off);
        d2 += __shfl_down_sync(0xFFFFFFFFu, d2, off);
    }
    if (lane == 0) { g_a[warp] = d1; g_c[warp] = d2; }
}

// ---------------- K2: per-batch segment scan --------------------------------
__global__ void k_scan(const float* __restrict__ bscore_p, float* __restrict__ out_tail) {
    int b   = blockIdx.x;
    int tid = threadIdx.x;
    float bs = *bscore_p;
    int t0 = tid * 2, t1 = t0 + 1;
    int s0 = (t0 == 0) ? 0
             : (((g_a[b * SS + t0 - 1] + g_c[b * SS + t0] + bs) > 0.5f) ? 0 : 1);
    int s1 = (((g_a[b * SS + t1 - 1] + g_c[b * SS + t1] + bs) > 0.5f) ? 0 : 1);

    __shared__ int sc[1024];
    sc[tid] = s0 + s1;
    __syncthreads();
    for (int off = 1; off < 1024; off <<= 1) {
        int v   = sc[tid];
        int add = (tid >= off) ? sc[tid - off] : 0;
        __syncthreads();
        sc[tid] = v + add;
        __syncthreads();
    }
    int excl = (tid == 0) ? 0 : sc[tid - 1];
    int seg0 = excl + s0;
    int seg1 = excl + s0 + s1;

    int base = b * (SS + 1);
    if (t0 == 0 || s0 == 1) g_segstart[base + seg0] = t0;
    if (s1 == 1)            g_segstart[base + seg1] = t1;
    if (t1 == SS - 1) {
        int nw = seg1 + 1;
        g_nwords[b] = nw;
        g_segstart[base + nw] = SS;
        if (out_tail) out_tail[b] = (float)nw;
    }
}

// ---------------- K3: segment means --------------------------------
__global__ void k_mean(const float* __restrict__ frame) {
    int j = blockIdx.x;
    int b = j / SS, w = j % SS;
    if (w >= g_nwords[b]) return;
    int base = b * (SS + 1);
    int st = g_segstart[base + w];
    int en = g_segstart[base + w + 1];
    float inv = 1.0f / (float)(en - st);
    int tid = threadIdx.x;
    float4 acc = make_float4(0.f, 0.f, 0.f, 0.f);
    for (int t = st; t < en; t++) {
        float4 f = ((const float4*)(frame + ((size_t)(b * SS + t)) * DD))[tid];
        acc.x += f.x; acc.y += f.y; acc.z += f.z; acc.w += f.w;
    }
    acc.x *= inv; acc.y *= inv; acc.z *= inv; acc.w *= inv;
    ((float4*)(g_mean + (size_t)j * DD))[tid] = acc;
}

// ---------------- K4: tf32 tensor-core GEMM --------------------------------
// words[b] = g_mean[b] @ w_comb + b_comb  (rows < nw), else 0.
// Block: 256 thr (8 warps, 4x2 warp grid). Tile 128x128, BK=16, double-buffered.
// mma.sync.aligned.m16n8k8.row.col.f32.tf32.tf32.f32

__device__ __forceinline__ uint32_t f2tf32(float v) {
    uint32_t r;
    asm("cvt.rna.tf32.f32 %0, %1;" : "=r"(r) : "f"(v));
    return r;
}

__device__ __forceinline__ void mma_tf32(float c[4], uint32_t a0, uint32_t a1,
                                         uint32_t a2, uint32_t a3,
                                         uint32_t b0, uint32_t b1) {
    asm volatile(
        "mma.sync.aligned.m16n8k8.row.col.f32.tf32.tf32.f32 "
        "{%0,%1,%2,%3}, {%4,%5,%6,%7}, {%8,%9}, {%0,%1,%2,%3};"
        : "+f"(c[0]), "+f"(c[1]), "+f"(c[2]), "+f"(c[3])
        : "r"(a0), "r"(a1), "r"(a2), "r"(a3), "r"(b0), "r"(b1));
}

__global__ void __launch_bounds__(256, 2)
k_gemm_tc(const float* __restrict__ wc, const float* __restrict__ bc,
          float* __restrict__ out) {
    int b    = blockIdx.z;
    int row0 = blockIdx.y * 128;
    int col0 = blockIdx.x * 128;
    int nw   = g_nwords[b];
    int tid  = threadIdx.x;
    float* outbase = out + (size_t)b * SS * DD;

    if (row0 >= nw) {
        // fully padded tile: zeros (d_out is poisoned 0xAA).
        float4 z = make_float4(0.f, 0.f, 0.f, 0.f);
        for (int i = tid; i < 128 * 32; i += 256) {
            int r = i >> 5, cq = i & 31;
            ((float4*)(outbase + (size_t)(row0 + r) * DD + col0))[cq] = z;
        }
        return;
    }

    __shared__ float As[2][128][20];   // [buf][row][k], pad 20 -> conflict-free frags
    __shared__ float Bs[2][16][132];   // [buf][k][col], pad 132

    const float* A = g_mean + (size_t)b * SS * DD;

    int wid  = tid >> 5;
    int lane = tid & 31;
    int wm   = wid & 3;        // warp row  (x32)
    int wn   = wid >> 2;       // warp col  (x64)
    int gid  = lane >> 2;      // 0..7
    int tq   = lane & 3;       // 0..3

    // global load indices (tile: A 128x16 = 512 f4; B 16x128 = 512 f4)
    int aid0 = tid, aid1 = tid + 256;
    int ar0 = aid0 >> 2, ak0 = (aid0 & 3) * 4;
    int ar1 = aid1 >> 2, ak1 = (aid1 & 3) * 4;
    int bk0 = aid0 >> 5, bn0 = (aid0 & 31) * 4;
    int bk1 = aid1 >> 5, bn1 = (aid1 & 31) * 4;

    float4 ra0, ra1, rb0, rb1;

    // prefetch tile 0
    {
        ra0 = *(const float4*)(A + (size_t)(row0 + ar0) * DD + ak0);
        ra1 = *(const float4*)(A + (size_t)(row0 + ar1) * DD + ak1);
        rb0 = *(const float4*)(wc + (size_t)bk0 * DD + col0 + bn0);
        rb1 = *(const float4*)(wc + (size_t)bk1 * DD + col0 + bn1);
    }
    // convert + store tile 0
    {
        uint4 u;
        u.x = f2tf32(ra0.x); u.y = f2tf32(ra0.y); u.z = f2tf32(ra0.z); u.w = f2tf32(ra0.w);
        *(uint4*)&As[0][ar0][ak0] = u;
        u.x = f2tf32(ra1.x); u.y = f2tf32(ra1.y); u.z = f2tf32(ra1.z); u.w = f2tf32(ra1.w);
        *(uint4*)&As[0][ar1][ak1] = u;
        u.x = f2tf32(rb0.x); u.y = f2tf32(rb0.y); u.z = f2tf32(rb0.z); u.w = f2tf32(rb0.w);
        *(uint4*)&Bs[0][bk0][bn0] = u;
        u.x = f2tf32(rb1.x); u.y = f2tf32(rb1.y); u.z = f2tf32(rb1.z); u.w = f2tf32(rb1.w);
        *(uint4*)&Bs[0][bk1][bn1] = u;
    }
    __syncthreads();

    float acc[2][8][4];
#pragma unroll
    for (int mt = 0; mt < 2; mt++)
#pragma unroll
        for (int nt = 0; nt < 8; nt++)
#pragma unroll
            for (int i = 0; i < 4; i++) acc[mt][nt][i] = 0.f;

    const int NKT = DD / 16;   // 32 K-tiles
    for (int kt = 0; kt < NKT; kt++) {
        int s = kt & 1;
        // prefetch next tile
        if (kt + 1 < NKT) {
            int k0 = (kt + 1) * 16;
            ra0 = *(const float4*)(A + (size_t)(row0 + ar0) * DD + k0 + ak0);
            ra1 = *(const float4*)(A + (size_t)(row0 + ar1) * DD + k0 + ak1);
            rb0 = *(const float4*)(wc + (size_t)(k0 + bk0) * DD + col0 + bn0);
            rb1 = *(const float4*)(wc + (size_t)(k0 + bk1) * DD + col0 + bn1);
        }
        // compute 2 k-steps of 8
#pragma unroll
        for (int ks = 0; ks < 2; ks++) {
            int k = ks * 8;
            uint32_t af[2][4];
#pragma unroll
            for (int mt = 0; mt < 2; mt++) {
                int rb = wm * 32 + mt * 16;
                af[mt][0] = __float_as_uint(As[s][rb + gid    ][k + tq    ]);
                af[mt][1] = __float_as_uint(As[s][rb + gid + 8][k + tq    ]);
                af[mt][2] = __float_as_uint(As[s][rb + gid    ][k + tq + 4]);
                af[mt][3] = __float_as_uint(As[s][rb + gid + 8][k + tq + 4]);
            }
            uint32_t bf[8][2];
#pragma unroll
            for (int nt = 0; nt < 8; nt++) {
                int nb = wn * 64 + nt * 8 + gid;
                bf[nt][0] = __float_as_uint(Bs[s][k + tq    ][nb]);
                bf[nt][1] = __float_as_uint(Bs[s][k + tq + 4][nb]);
            }
#pragma unroll
            for (int mt = 0; mt < 2; mt++)
#pragma unroll
                for (int nt = 0; nt < 8; nt++)
                    mma_tf32(acc[mt][nt], af[mt][0], af[mt][1], af[mt][2], af[mt][3],
                             bf[nt][0], bf[nt][1]);
        }
        // store next tile
        if (kt + 1 < NKT) {
            int sn = (kt + 1) & 1;
            uint4 u;
            u.x = f2tf32(ra0.x); u.y = f2tf32(ra0.y); u.z = f2tf32(ra0.z); u.w = f2tf32(ra0.w);
            *(uint4*)&As[sn][ar0][ak0] = u;
            u.x = f2tf32(ra1.x); u.y = f2tf32(ra1.y); u.z = f2tf32(ra1.z); u.w = f2tf32(ra1.w);
            *(uint4*)&As[sn][ar1][ak1] = u;
            u.x = f2tf32(rb0.x); u.y = f2tf32(rb0.y); u.z = f2tf32(rb0.z); u.w = f2tf32(rb0.w);
            *(uint4*)&Bs[sn][bk0][bn0] = u;
            u.x = f2tf32(rb1.x); u.y = f2tf32(rb1.y); u.z = f2tf32(rb1.z); u.w = f2tf32(rb1.w);
            *(uint4*)&Bs[sn][bk1][bn1] = u;
            __syncthreads();
        }
    }

    // epilogue: add bias, zero rows >= nw, write float2 per (reg pair)
#pragma unroll
    for (int mt = 0; mt < 2; mt++) {
        int r0g = row0 + wm * 32 + mt * 16 + gid;
        int r1g = r0g + 8;
#pragma unroll
        for (int nt = 0; nt < 8; nt++) {
            int col = col0 + wn * 64 + nt * 8 + 2 * tq;
            float2 bias = *(const float2*)(bc + col);
            float2 v0, v1;
            if (r0g < nw) {
                v0.x = acc[mt][nt][0] + bias.x;
                v0.y = acc[mt][nt][1] + bias.y;
            } else { v0.x = 0.f; v0.y = 0.f; }
            if (r1g < nw) {
                v1.x = acc[mt][nt][2] + bias.x;
                v1.y = acc[mt][nt][3] + bias.y;
            } else { v1.x = 0.f; v1.y = 0.f; }
            *(float2*)(outbase + (size_t)r0g * DD + col) = v0;
            *(float2*)(outbase + (size_t)r1g * DD + col) = v1;
        }
    }
}

// ---------------- launcher ----------------
extern "C" void kernel_launch(void* const* d_in, const int* in_sizes, int n_in,
                              void* d_out, int out_size) {
    const float* frame  = (const float*)d_in[0];   // [B,S,D]
    const float* wscore = (const float*)d_in[1];   // [2D,1]
    const float* bscore = (const float*)d_in[2];   // [1]
    const float* wcomb  = (const float*)d_in[3];   // [D,D]
    const float* bcomb  = (const float*)d_in[4];   // [D]
    float* out = (float*)d_out;

    float* tail = (out_size >= BB * SS * DD + BB) ? out + (size_t)BB * SS * DD : nullptr;

    k_scores<<<(BB * SS) / 8, 256>>>(frame, wscore);
    k_scan<<<BB, 1024>>>(bscore, tail);
    k_mean<<<BB * SS, 128>>>(frame);
    dim3 grid(DD / 128, SS / 128, BB);
    k_gemm_tc<<<grid, 256>>>(wcomb, bcomb, out);
}

// round 7
// speedup vs baseline: 2.8279x; 1.1163x over previous
#include <cuda_runtime.h>
#include <cstdint>

#define BB 16
#define SS 2048
#define DD 512
#define NST 4                      // cp.async pipeline stages
#define ROWSTR 24                  // smem row stride in floats (16 data + 8 pad)
#define STAGE_F (128 * ROWSTR)     // floats per stage per operand (3072)

// ---------------- device scratch ----------------
__device__ float g_a[BB * SS];
__device__ float g_c[BB * SS];
__device__ int   g_segstart[BB * (SS + 1)];
__device__ int   g_nwords[BB];
__device__ float g_mean[(size_t)BB * SS * DD];   // tf32-rounded, k-pair-permuted means
__device__ float g_wcT[DD * DD];                 // w_comb^T [N][K], tf32-rounded, permuted

__device__ __forceinline__ uint32_t f2tf32(float v) {
    uint32_t r;
    asm("cvt.rna.tf32.f32 %0, %1;" : "=r"(r) : "f"(v));
    return r;
}
__device__ __forceinline__ uint32_t smem_u32(const void* p) {
    uint32_t a;
    asm("{ .reg .u64 t; cvta.to.shared.u64 t, %1; cvt.u32.u64 %0, t; }" : "=r"(a) : "l"(p));
    return a;
}
#define CP16(dst, src) \
    asm volatile("cp.async.cg.shared.global [%0], [%1], 16;" :: "r"(dst), "l"(src))
#define CP_COMMIT() asm volatile("cp.async.commit_group;" ::: "memory")
#define CP_WAIT2()  asm volatile("cp.async.wait_group 2;" ::: "memory")

__device__ __forceinline__ void mma_tf32(float c[4], uint32_t a0, uint32_t a1,
                                         uint32_t a2, uint32_t a3,
                                         uint32_t b0, uint32_t b1) {
    asm volatile(
        "mma.sync.aligned.m16n8k8.row.col.f32.tf32.tf32.f32 "
        "{%0,%1,%2,%3}, {%4,%5,%6,%7}, {%8,%9}, {%0,%1,%2,%3};"
        : "+f"(c[0]), "+f"(c[1]), "+f"(c[2]), "+f"(c[3])
        : "r"(a0), "r"(a1), "r"(a2), "r"(a3), "r"(b0), "r"(b1));
}

// ---------------- K1: per-frame score dots ----------------
__global__ void k_scores(const float* __restrict__ frame, const float* __restrict__ wscore) {
    int warp = (blockIdx.x * blockDim.x + threadIdx.x) >> 5;
    int lane = threadIdx.x & 31;
    if (warp >= BB * SS) return;
    const float4* row = (const float4*)(frame + (size_t)warp * DD);
    const float4* w1  = (const float4*)wscore;
    const float4* w2  = (const float4*)(wscore + DD);
    float d1 = 0.f, d2 = 0.f;
#pragma unroll
    for (int k = 0; k < 4; k++) {
        int i = lane + k * 32;
        float4 f = row[i];
        float4 a = w1[i];
        float4 b = w2[i];
        d1 += f.x * a.x + f.y * a.y + f.z * a.z + f.w * a.w;
        d2 += f.x * b.x + f.y * b.y + f.z * b.z + f.w * b.w;
    }
#pragma unroll
    for (int off = 16; off; off >>= 1) {
        d1 += __shfl_down_sync(0xFFFFFFFFu, d1, off);
        d2 += __shfl_down_sync(0xFFFFFFFFu, d2, off);
    }
    if (lane == 0) { g_a[warp] = d1; g_c[warp] = d2; }
}

// ---------------- K2: per-batch segment scan ----------------
__global__ void k_scan(const float* __restrict__ bscore_p, float* __restrict__ out_tail) {
    int b   = blockIdx.x;
    int tid = threadIdx.x;
    float bs = *bscore_p;
    int t0 = tid * 2, t1 = t0 + 1;
    int s0 = (t0 == 0) ? 0
             : (((g_a[b * SS + t0 - 1] + g_c[b * SS + t0] + bs) > 0.5f) ? 0 : 1);
    int s1 = (((g_a[b * SS + t1 - 1] + g_c[b * SS + t1] + bs) > 0.5f) ? 0 : 1);

    __shared__ int sc[1024];
    sc[tid] = s0 + s1;
    __syncthreads();
    for (int off = 1; off < 1024; off <<= 1) {
        int v   = sc[tid];
        int add = (tid >= off) ? sc[tid - off] : 0;
        __syncthreads();
        sc[tid] = v + add;
        __syncthreads();
    }
    int excl = (tid == 0) ? 0 : sc[tid - 1];
    int seg0 = excl + s0;
    int seg1 = excl + s0 + s1;

    int base = b * (SS + 1);
    if (t0 == 0 || s0 == 1) g_segstart[base + seg0] = t0;
    if (s1 == 1)            g_segstart[base + seg1] = t1;
    if (t1 == SS - 1) {
        int nw = seg1 + 1;
        g_nwords[b] = nw;
        g_segstart[base + nw] = SS;
        if (out_tail) out_tail[b] = (float)nw;
    }
}

// ---------------- K3: segment means (tf32-rounded, k-pair-permuted) ----------------
// 64 threads/block; thread g owns k-group 8g..8g+7. Permuted store order:
// (k0,k4,k1,k5) (k2,k6,k3,k7) so fragment pairs (tq, tq+4) are contiguous.
__global__ void k_mean(const float* __restrict__ frame) {
    int j = blockIdx.x;
    int b = j / SS, w = j % SS;
    if (w >= g_nwords[b]) return;
    int base = b * (SS + 1);
    int st = g_segstart[base + w];
    int en = g_segstart[base + w + 1];
    float inv = 1.0f / (float)(en - st);
    int g = threadIdx.x;                       // 0..63
    float a[8];
#pragma unroll
    for (int i = 0; i < 8; i++) a[i] = 0.f;
    for (int t = st; t < en; t++) {
        const float4* p = (const float4*)(frame + ((size_t)(b * SS + t)) * DD + g * 8);
        float4 v0 = p[0], v1 = p[1];
        a[0] += v0.x; a[1] += v0.y; a[2] += v0.z; a[3] += v0.w;
        a[4] += v1.x; a[5] += v1.y; a[6] += v1.z; a[7] += v1.w;
    }
    uint4 o0, o1;
    o0.x = f2tf32(a[0] * inv); o0.y = f2tf32(a[4] * inv);
    o0.z = f2tf32(a[1] * inv); o0.w = f2tf32(a[5] * inv);
    o1.x = f2tf32(a[2] * inv); o1.y = f2tf32(a[6] * inv);
    o1.z = f2tf32(a[3] * inv); o1.w = f2tf32(a[7] * inv);
    uint4* dst = (uint4*)(g_mean + (size_t)j * DD + g * 8);
    dst[0] = o0;
    dst[1] = o1;
}

// ---------------- K3b: w_comb -> g_wcT[N][K] transposed, rounded, permuted ----------
__global__ void k_wcT(const float* __restrict__ wc) {
    __shared__ float t[32][33];
    int k0 = blockIdx.y * 32, n0 = blockIdx.x * 32;
    int x = threadIdx.x, y0 = threadIdx.y;     // 32 x 8
#pragma unroll
    for (int dy = 0; dy < 32; dy += 8)
        t[y0 + dy][x] = wc[(size_t)(k0 + y0 + dy) * DD + n0 + x];
    __syncthreads();
#pragma unroll
    for (int dy = 0; dy < 32; dy += 8) {
        int k = k0 + x;                        // original k of this element
        int kp = (k & ~7) | (2 * (k & 3)) | ((k >> 2) & 1);
        g_wcT[(size_t)(n0 + y0 + dy) * DD + kp] =
            __uint_as_float(f2tf32(t[x][y0 + dy]));
    }
}

// ---------------- K4: tf32 mma.sync GEMM, cp.async 4-stage, LDS.64 frags --------
__global__ void __launch_bounds__(256, 2)
k_gemm_tc(const float* __restrict__ bc, float* __restrict__ out) {
    int b    = blockIdx.z;
    int row0 = blockIdx.y * 128;
    int col0 = blockIdx.x * 128;
    int nw   = g_nwords[b];
    int tid  = threadIdx.x;
    float* outbase = out + (size_t)b * SS * DD;

    if (row0 >= nw) {
        float4 z = make_float4(0.f, 0.f, 0.f, 0.f);
        for (int i = tid; i < 128 * 32; i += 256) {
            int r = i >> 5, cq = i & 31;
            ((float4*)(outbase + (size_t)(row0 + r) * DD + col0))[cq] = z;
        }
        return;
    }

    extern __shared__ float sm[];
    float* AsB = sm;                         // NST * STAGE_F
    float* BsB = sm + NST * STAGE_F;

    const float* A  = g_mean + ((size_t)b * SS + row0) * DD;
    const float* Bm = g_wcT + (size_t)col0 * DD;

    // cp.async chunk mapping: 512 16B-chunks per operand per stage, 2 per thread.
    int id0 = tid, id1 = tid + 256;
    int r0c = id0 >> 2, c0c = id0 & 3;       // (row, 16B-chunk-in-row)
    int r1c = id1 >> 2, c1c = id1 & 3;

    uint32_t aA = smem_u32(AsB), aB = smem_u32(BsB);
    // byte offsets within a stage
    uint32_t dA0 = r0c * (ROWSTR * 4) + c0c * 16;
    uint32_t dA1 = r1c * (ROWSTR * 4) + c1c * 16;

    int wid  = tid >> 5;
    int lane = tid & 31;
    int wm   = wid & 3;                      // warp row (x32)
    int wn   = wid >> 2;                     // warp col (x64)
    int gid  = lane >> 2;
    int tq   = lane & 3;

    float acc[2][8][4];
#pragma unroll
    for (int mt = 0; mt < 2; mt++)
#pragma unroll
        for (int nt = 0; nt < 8; nt++)
#pragma unroll
            for (int i = 0; i < 4; i++) acc[mt][nt][i] = 0.f;

    // prologue: issue stages 0..2
#pragma unroll
    for (int p = 0; p < 3; p++) {
        uint32_t sb = p * (STAGE_F * 4);
        CP16(aA + sb + dA0, A + (size_t)r0c * DD + p * 16 + c0c * 4);
        CP16(aA + sb + dA1, A + (size_t)r1c * DD + p * 16 + c1c * 4);
        CP16(aB + sb + dA0, Bm + (size_t)r0c * DD + p * 16 + c0c * 4);
        CP16(aB + sb + dA1, Bm + (size_t)r1c * DD + p * 16 + c1c * 4);
        CP_COMMIT();
    }

    const int NKT = DD / 16;                 // 32
    for (int kt = 0; kt < NKT; kt++) {
        CP_WAIT2();
        __syncthreads();

        // issue stage kt+3 (into the slot consumed at kt-1)
        if (kt + 3 < NKT) {
            int p = kt + 3;
            uint32_t sb = (p & 3) * (STAGE_F * 4);
            CP16(aA + sb + dA0, A + (size_t)r0c * DD + p * 16 + c0c * 4);
            CP16(aA + sb + dA1, A + (size_t)r1c * DD + p * 16 + c1c * 4);
            CP16(aB + sb + dA0, Bm + (size_t)r0c * DD + p * 16 + c0c * 4);
            CP16(aB + sb + dA1, Bm + (size_t)r1c * DD + p * 16 + c1c * 4);
        }
        CP_COMMIT();

        const float* as = AsB + (kt & 3) * STAGE_F;
        const float* bs = BsB + (kt & 3) * STAGE_F;
#pragma unroll
        for (int ks = 0; ks < 2; ks++) {
            int ko = ks * 8 + 2 * tq;
            uint32_t af[2][4];
#pragma unroll
            for (int mt = 0; mt < 2; mt++) {
                int rb = wm * 32 + mt * 16 + gid;
                float2 p0 = *(const float2*)(as + rb * ROWSTR + ko);
                float2 p1 = *(const float2*)(as + (rb + 8) * ROWSTR + ko);
                af[mt][0] = __float_as_uint(p0.x);
                af[mt][1] = __float_as_uint(p1.x);
                af[mt][2] = __float_as_uint(p0.y);
                af[mt][3] = __float_as_uint(p1.y);
            }
            uint32_t bf[8][2];
#pragma unroll
            for (int nt = 0; nt < 8; nt++) {
                int nb = wn * 64 + nt * 8 + gid;
                float2 q = *(const float2*)(bs + nb * ROWSTR + ko);
                bf[nt][0] = __float_as_uint(q.x);
                bf[nt][1] = __float_as_uint(q.y);
            }
#pragma unroll
            for (int mt = 0; mt < 2; mt++)
#pragma unroll
                for (int nt = 0; nt < 8; nt++)
                    mma_tf32(acc[mt][nt], af[mt][0], af[mt][1], af[mt][2], af[mt][3],
                             bf[nt][0], bf[nt][1]);
        }
    }

    // epilogue: bias + zero padded rows, direct stores
#pragma unroll
    for (int mt = 0; mt < 2; mt++) {
        int r0g = row0 + wm * 32 + mt * 16 + gid;
        int r1g = r0g + 8;
#pragma unroll
        for (int nt = 0; nt < 8; nt++) {
            int col = col0 + wn * 64 + nt * 8 + 2 * tq;
            float2 bias = *(const float2*)(bc + col);
            float2 v0, v1;
            if (r0g < nw) {
                v0.x = acc[mt][nt][0] + bias.x;
                v0.y = acc[mt][nt][1] + bias.y;
            } else { v0.x = 0.f; v0.y = 0.f; }
            if (r1g < nw) {
                v1.x = acc[mt][nt][2] + bias.x;
                v1.y = acc[mt][nt][3] + bias.y;
            } else { v1.x = 0.f; v1.y = 0.f; }
            *(float2*)(outbase + (size_t)r0g * DD + col) = v0;
            *(float2*)(outbase + (size_t)r1g * DD + col) = v1;
        }
    }
}

// ---------------- launcher ----------------
extern "C" void kernel_launch(void* const* d_in, const int* in_sizes, int n_in,
                              void* d_out, int out_size) {
    const float* frame  = (const float*)d_in[0];   // [B,S,D]
    const float* wscore = (const float*)d_in[1];   // [2D,1]
    const float* bscore = (const float*)d_in[2];   // [1]
    const float* wcomb  = (const float*)d_in[3];   // [D,D]
    const float* bcomb  = (const float*)d_in[4];   // [D]
    float* out = (float*)d_out;

    float* tail = (out_size >= BB * SS * DD + BB) ? out + (size_t)BB * SS * DD : nullptr;

    const int SMEM_DYN = 2 * NST * STAGE_F * 4;    // 98304 B
    cudaFuncSetAttribute(k_gemm_tc, cudaFuncAttributeMaxDynamicSharedMemorySize, SMEM_DYN);

    k_wcT<<<dim3(DD / 32, DD / 32), dim3(32, 8)>>>(wcomb);
    k_scores<<<(BB * SS) / 8, 256>>>(frame, wscore);
    k_scan<<<BB, 1024>>>(bscore, tail);
    k_mean<<<BB * SS, 64>>>(frame);
    dim3 grid(DD / 128, SS / 128, BB);
    k_gemm_tc<<<grid, 256, SMEM_DYN>>>(bcomb, out);
}